// round 11
// baseline (speedup 1.0000x reference)
#include <cuda_runtime.h>
#include <cuda_bf16.h>
#include <cstdint>

// ROI pooling: crop_and_resize (bilinear, 14x14) + 2x2 max pool -> (N,7,7,512)
// feature_map: (1, 50, 75, 512) fp32 NHWC ; rois: (N,4) [x1,y1,x2,y2] ; img_size: (2,) int32
//
// grid = (N, 7 pooled rows), block = 128 threads (one float4 of channels/thread).
// cp.async (LDGSTS.ca) software pipeline, sample granularity, 2-stage smem ring.
// Each thread copies and reads back ITS OWN 16B per column slot -> thread-private
// smem, no __syncthreads, only cp.async.wait_group. Outstanding loads live in
// smem, not registers, so MLP is no longer register-bound. Shared-middle-row
// dedup (6 vs 8 loads/sample) kept as two hoisted branch-free paths.

#define FH 50
#define FW 75
#define FC 512
#define NPOOL 7
#define CROPDIM 14
#define C4 (FC / 4)
#define ROWSTRIDE (FW * C4)

__device__ __forceinline__ void cpa16(uint32_t saddr, const float4* g) {
    asm volatile("cp.async.ca.shared.global [%0], [%1], 16;"
                 :: "r"(saddr), "l"(g) : "memory");
}
__device__ __forceinline__ void cp_commit() {
    asm volatile("cp.async.commit_group;" ::: "memory");
}
template <int N>
__device__ __forceinline__ void cp_wait() {
    asm volatile("cp.async.wait_group %0;" :: "n"(N) : "memory");
}

__device__ __forceinline__ float4 lerp4(const float4 a, const float4 b,
                                        const float wa, const float wb) {
    float4 h;
    h.x = fmaf(b.x, wb, a.x * wa);
    h.y = fmaf(b.y, wb, a.y * wa);
    h.z = fmaf(b.z, wb, a.z * wa);
    h.w = fmaf(b.w, wb, a.w * wa);
    return h;
}

__device__ __forceinline__ float4 max4(const float4 a, const float4 b) {
    float4 m;
    m.x = fmaxf(a.x, b.x);
    m.y = fmaxf(a.y, b.y);
    m.z = fmaxf(a.z, b.z);
    m.w = fmaxf(a.w, b.w);
    return m;
}

struct XCol {
    int   cA, cB;
    float wxg, omwxg;
};

__device__ __forceinline__ XCol xcol(const int k, const float sx, const float xb,
                                     const float fw) {
    XCol c;
    const float xs = fmaf((float)k, sx, xb);
    const float gx = ((xs >= 0.0f) && (xs <= fw)) ? 1.0f : 0.0f;
    const float x0 = floorf(xs);
    const float wx = xs - x0;
    int xi = min(max((int)x0, 0), FW - 1);
    c.cA = xi * C4;
    c.cB = min(xi + 1, FW - 1) * C4;
    c.wxg   = wx * gx;
    c.omwxg = (1.0f - wx) * gx;
    return c;
}

// smem ring: [stage 0/1][col slot 0..7][tid] float4  = 32 KB
#define SLOT_BYTES   (128 * 16)            // one column slot (all 128 threads)
#define STAGE_BYTES  (8 * SLOT_BYTES)      // 8 slots per stage

__global__ __launch_bounds__(128) void roi_pool_kernel(
    const float* __restrict__ fmap,
    const float* __restrict__ rois,
    const int*   __restrict__ img_size,
    float*       __restrict__ out)
{
    __shared__ float4 stage[2][8][128];

    const int n   = blockIdx.x;   // roi index
    const int py  = blockIdx.y;   // pooled row 0..6
    const int tid = threadIdx.x;  // float4 channel chunk 0..127

    // ---- uniform per-block scalar setup ----
    const float ih = (float)img_size[0] - 1.0f;   // 799
    const float iw = (float)img_size[1] - 1.0f;   // 1199
    const float4 r = reinterpret_cast<const float4*>(rois)[n]; // x1,y1,x2,y2
    const float bx1 = r.x / iw;
    const float by1 = r.y / ih;
    const float bx2 = r.z / iw;
    const float by2 = r.w / ih;

    const float fh = (float)(FH - 1);   // 49
    const float fw = (float)(FW - 1);   // 74
    const float sy = (by2 - by1) * fh * (1.0f / (CROPDIM - 1));
    const float sx = (bx2 - bx1) * fw * (1.0f / (CROPDIM - 1));
    const float yb = by1 * fh;
    const float xb = bx1 * fw;

    // two crop rows feeding this pooled row (uniform scalars)
    int   row0, row1, row2, row3;
    float wyg0, omwyg0, wyg1, omwyg1;
    {
        const float ys0 = fmaf((float)(2 * py), sy, yb);
        const float gy0 = ((ys0 >= 0.0f) && (ys0 <= fh)) ? 1.0f : 0.0f;
        const float fl0 = floorf(ys0);
        const float wy0 = ys0 - fl0;
        int yi0 = min(max((int)fl0, 0), FH - 1);
        row0 = yi0 * ROWSTRIDE;
        row1 = min(yi0 + 1, FH - 1) * ROWSTRIDE;
        wyg0 = wy0 * gy0;  omwyg0 = (1.0f - wy0) * gy0;

        const float ys1 = fmaf((float)(2 * py + 1), sy, yb);
        const float gy1 = ((ys1 >= 0.0f) && (ys1 <= fh)) ? 1.0f : 0.0f;
        const float fl1 = floorf(ys1);
        const float wy1 = ys1 - fl1;
        int yi1 = min(max((int)fl1, 0), FH - 1);
        row2 = yi1 * ROWSTRIDE;
        row3 = min(yi1 + 1, FH - 1) * ROWSTRIDE;
        wyg1 = wy1 * gy1;  omwyg1 = (1.0f - wy1) * gy1;
    }

    const float4* __restrict__ fb = reinterpret_cast<const float4*>(fmap) + tid;
    float4* __restrict__ ob = reinterpret_cast<float4*>(out)
        + ((long)n * (NPOOL * NPOOL) + py * NPOOL) * C4 + tid;

    const uint32_t sb = (uint32_t)__cvta_generic_to_shared(stage) + tid * 16u;

    float wxgR[2], omwxgR[2];   // per-stage consume weights (const-indexed, stays in regs)
    float4 macc;

    if (row2 == row1) {
        // ================= shared middle feature row: 6 loads / sample =================
        {   // prologue: issue sample 0 into stage 0
            const XCol c = xcol(0, sx, xb, fw);
            const uint32_t a = sb;
            cpa16(a + 0 * SLOT_BYTES, fb + row0 + c.cA);
            cpa16(a + 1 * SLOT_BYTES, fb + row0 + c.cB);
            cpa16(a + 2 * SLOT_BYTES, fb + row1 + c.cA);
            cpa16(a + 3 * SLOT_BYTES, fb + row1 + c.cB);
            cpa16(a + 4 * SLOT_BYTES, fb + row3 + c.cA);
            cpa16(a + 5 * SLOT_BYTES, fb + row3 + c.cB);
            cp_commit();
            wxgR[0] = c.wxg;  omwxgR[0] = c.omwxg;
        }
#pragma unroll
        for (int s = 0; s < CROPDIM; s++) {
            const int buf = s & 1;
            if (s < CROPDIM - 1) {
                const int nb = (s + 1) & 1;
                const XCol c = xcol(s + 1, sx, xb, fw);
                const uint32_t a = sb + nb * STAGE_BYTES;
                cpa16(a + 0 * SLOT_BYTES, fb + row0 + c.cA);
                cpa16(a + 1 * SLOT_BYTES, fb + row0 + c.cB);
                cpa16(a + 2 * SLOT_BYTES, fb + row1 + c.cA);
                cpa16(a + 3 * SLOT_BYTES, fb + row1 + c.cB);
                cpa16(a + 4 * SLOT_BYTES, fb + row3 + c.cA);
                cpa16(a + 5 * SLOT_BYTES, fb + row3 + c.cB);
                cp_commit();
                wxgR[nb] = c.wxg;  omwxgR[nb] = c.omwxg;
                cp_wait<1>();
            } else {
                cp_wait<0>();
            }
            const float wxg = wxgR[buf], omwxg = omwxgR[buf];
            const float4 a0 = stage[buf][0][tid];
            const float4 b0 = stage[buf][1][tid];
            const float4 a1 = stage[buf][2][tid];
            const float4 b1 = stage[buf][3][tid];
            const float4 a3 = stage[buf][4][tid];
            const float4 b3 = stage[buf][5][tid];
            const float4 h0 = lerp4(a0, b0, omwxg, wxg);
            const float4 h1 = lerp4(a1, b1, omwxg, wxg);
            const float4 h3 = lerp4(a3, b3, omwxg, wxg);
            const float4 v = max4(lerp4(h0, h1, omwyg0, wyg0),
                                  lerp4(h1, h3, omwyg1, wyg1));
            if ((s & 1) == 0) macc = v;
            else              ob[(s >> 1) * C4] = max4(macc, v);
        }
    } else {
        // ================= generic: 4 distinct rows, 8 loads / sample =================
        {   // prologue
            const XCol c = xcol(0, sx, xb, fw);
            const uint32_t a = sb;
            cpa16(a + 0 * SLOT_BYTES, fb + row0 + c.cA);
            cpa16(a + 1 * SLOT_BYTES, fb + row0 + c.cB);
            cpa16(a + 2 * SLOT_BYTES, fb + row1 + c.cA);
            cpa16(a + 3 * SLOT_BYTES, fb + row1 + c.cB);
            cpa16(a + 4 * SLOT_BYTES, fb + row2 + c.cA);
            cpa16(a + 5 * SLOT_BYTES, fb + row2 + c.cB);
            cpa16(a + 6 * SLOT_BYTES, fb + row3 + c.cA);
            cpa16(a + 7 * SLOT_BYTES, fb + row3 + c.cB);
            cp_commit();
            wxgR[0] = c.wxg;  omwxgR[0] = c.omwxg;
        }
#pragma unroll
        for (int s = 0; s < CROPDIM; s++) {
            const int buf = s & 1;
            if (s < CROPDIM - 1) {
                const int nb = (s + 1) & 1;
                const XCol c = xcol(s + 1, sx, xb, fw);
                const uint32_t a = sb + nb * STAGE_BYTES;
                cpa16(a + 0 * SLOT_BYTES, fb + row0 + c.cA);
                cpa16(a + 1 * SLOT_BYTES, fb + row0 + c.cB);
                cpa16(a + 2 * SLOT_BYTES, fb + row1 + c.cA);
                cpa16(a + 3 * SLOT_BYTES, fb + row1 + c.cB);
                cpa16(a + 4 * SLOT_BYTES, fb + row2 + c.cA);
                cpa16(a + 5 * SLOT_BYTES, fb + row2 + c.cB);
                cpa16(a + 6 * SLOT_BYTES, fb + row3 + c.cA);
                cpa16(a + 7 * SLOT_BYTES, fb + row3 + c.cB);
                cp_commit();
                wxgR[nb] = c.wxg;  omwxgR[nb] = c.omwxg;
                cp_wait<1>();
            } else {
                cp_wait<0>();
            }
            const float wxg = wxgR[buf], omwxg = omwxgR[buf];
            const float4 a0 = stage[buf][0][tid];
            const float4 b0 = stage[buf][1][tid];
            const float4 a1 = stage[buf][2][tid];
            const float4 b1 = stage[buf][3][tid];
            const float4 a2 = stage[buf][4][tid];
            const float4 b2 = stage[buf][5][tid];
            const float4 a3 = stage[buf][6][tid];
            const float4 b3 = stage[buf][7][tid];
            const float4 h0 = lerp4(a0, b0, omwxg, wxg);
            const float4 h1 = lerp4(a1, b1, omwxg, wxg);
            const float4 h2 = lerp4(a2, b2, omwxg, wxg);
            const float4 h3 = lerp4(a3, b3, omwxg, wxg);
            const float4 v = max4(lerp4(h0, h1, omwyg0, wyg0),
                                  lerp4(h2, h3, omwyg1, wyg1));
            if ((s & 1) == 0) macc = v;
            else              ob[(s >> 1) * C4] = max4(macc, v);
        }
    }
}

extern "C" void kernel_launch(void* const* d_in, const int* in_sizes, int n_in,
                              void* d_out, int out_size) {
    const float* fmap     = (const float*)d_in[0];
    const float* rois     = (const float*)d_in[1];
    const int*   img_size = (const int*)d_in[2];
    float* out = (float*)d_out;

    const int N = in_sizes[1] / 4;   // number of rois
    dim3 grid(N, NPOOL);
    roi_pool_kernel<<<grid, 128>>>(fmap, rois, img_size, out);
}

// round 12
// speedup vs baseline: 1.7799x; 1.7799x over previous
#include <cuda_runtime.h>
#include <cuda_bf16.h>
#include <float.h>

// ROI pooling: crop_and_resize (bilinear, 14x14) + 2x2 max pool -> (N,7,7,512)
// feature_map: (1, 50, 75, 512) fp32 NHWC ; rois: (N,4) [x1,y1,x2,y2] ; img_size: (2,) int32
//
// grid = (N, 7 pooled COLUMNS), block = 128 threads (one float4 of channels/thread).
// Each block fixes its 2 x-samples (4 columns) and walks the distinct feature rows
// of the roi once (avg ~18 rows): per feature row, 4 LDG.128 + 2 horizontal lerps;
// crop rows emit (vertical lerp of h_prev/h_cur) when the walk reaches their ceil
// feature row. Emissions are in crop-row order, so one pending register implements
// the 2x2 max pool. All bookkeeping is block-uniform scalar.
// ~73 loads/block vs 92 for the per-pooled-row scheme.

#define FH 50
#define FW 75
#define FC 512
#define NPOOL 7
#define CROPDIM 14
#define C4 (FC / 4)
#define ROWSTRIDE (FW * C4)

__device__ __forceinline__ float4 lerp4(const float4 a, const float4 b,
                                        const float wa, const float wb) {
    float4 h;
    h.x = fmaf(b.x, wb, a.x * wa);
    h.y = fmaf(b.y, wb, a.y * wa);
    h.z = fmaf(b.z, wb, a.z * wa);
    h.w = fmaf(b.w, wb, a.w * wa);
    return h;
}

__device__ __forceinline__ float4 max4(const float4 a, const float4 b) {
    float4 m;
    m.x = fmaxf(a.x, b.x);
    m.y = fmaxf(a.y, b.y);
    m.z = fmaxf(a.z, b.z);
    m.w = fmaxf(a.w, b.w);
    return m;
}

// per-crop-row uniform info: ceil feature row (emission point) + lerp weights
__device__ __forceinline__ void tinfo(const int t, const float sy, const float yb,
                                      const float fh,
                                      int& rA, int& rB, float& wP, float& wC) {
    const float ys = fmaf((float)t, sy, yb);
    const float gy = ((ys >= 0.0f) && (ys <= fh)) ? 1.0f : 0.0f;
    const float fl = floorf(ys);
    const float wy = ys - fl;
    int a = min(max((int)fl, 0), FH - 1);
    int b = min(a + 1, FH - 1);
    const float wyg   = wy * gy;
    const float omwyg = (1.0f - wy) * gy;
    rA = a; rB = b;
    if (a == b) { wP = 0.0f; wC = wyg + omwyg; }   // clamped: both taps on same row
    else        { wP = omwyg; wC = wyg; }
}

__global__ __launch_bounds__(128) void roi_pool_kernel(
    const float* __restrict__ fmap,
    const float* __restrict__ rois,
    const int*   __restrict__ img_size,
    float*       __restrict__ out)
{
    const int n   = blockIdx.x;   // roi index
    const int px  = blockIdx.y;   // pooled column 0..6
    const int tid = threadIdx.x;  // float4 channel chunk 0..127

    // ---- uniform per-block scalar setup ----
    const float ih = (float)img_size[0] - 1.0f;   // 799
    const float iw = (float)img_size[1] - 1.0f;   // 1199
    const float4 r = reinterpret_cast<const float4*>(rois)[n]; // x1,y1,x2,y2
    const float bx1 = r.x / iw;
    const float by1 = r.y / ih;
    const float bx2 = r.z / iw;
    const float by2 = r.w / ih;

    const float fh = (float)(FH - 1);   // 49
    const float fw = (float)(FW - 1);   // 74
    const float sy = (by2 - by1) * fh * (1.0f / (CROPDIM - 1));
    const float sx = (bx2 - bx1) * fw * (1.0f / (CROPDIM - 1));
    const float yb = by1 * fh;
    const float xb = bx1 * fw;

    // ---- the block's 2 x-samples (4 column offsets, uniform) ----
    int   cA0, cB0, cA1, cB1;
    float wx0, omwx0, wx1, omwx1;
    {
        const float xs0 = fmaf((float)(2 * px), sx, xb);
        const float gx0 = ((xs0 >= 0.0f) && (xs0 <= fw)) ? 1.0f : 0.0f;
        const float f0 = floorf(xs0);
        int xi0 = min(max((int)f0, 0), FW - 1);
        cA0 = xi0 * C4;  cB0 = min(xi0 + 1, FW - 1) * C4;
        wx0 = (xs0 - f0) * gx0;  omwx0 = (1.0f - (xs0 - f0)) * gx0;

        const float xs1 = fmaf((float)(2 * px + 1), sx, xb);
        const float gx1 = ((xs1 >= 0.0f) && (xs1 <= fw)) ? 1.0f : 0.0f;
        const float f1 = floorf(xs1);
        int xi1 = min(max((int)f1, 0), FW - 1);
        cA1 = xi1 * C4;  cB1 = min(xi1 + 1, FW - 1) * C4;
        wx1 = (xs1 - f1) * gx1;  omwx1 = (1.0f - (xs1 - f1)) * gx1;
    }

    const float4* __restrict__ fb = reinterpret_cast<const float4*>(fmap) + tid;
    float4* __restrict__ ob = reinterpret_cast<float4*>(out)
        + ((long)n * (NPOOL * NPOOL) + px) * C4 + tid;

    // ---- y walk ----
    int   tptr = 0;
    int   trA, trB;
    float twP, twC;
    tinfo(0, sy, yb, fh, trA, trB, twP, twC);
    int fr = trA;

    float4 hp0 = make_float4(0.f, 0.f, 0.f, 0.f);
    float4 hp1 = hp0;
    float4 pend0 = hp0, pend1 = hp0;

    while (tptr < CROPDIM) {
        // load feature row fr's 4 columns, horizontal lerps (the only vector loads)
        const float4* rp = fb + fr * ROWSTRIDE;
        const float4 l0 = __ldg(rp + cA0);
        const float4 l1 = __ldg(rp + cB0);
        const float4 l2 = __ldg(rp + cA1);
        const float4 l3 = __ldg(rp + cB1);
        const float4 h0 = lerp4(l0, l1, omwx0, wx0);
        const float4 h1 = lerp4(l2, l3, omwx1, wx1);

        // emit every crop row whose ceil feature row is fr (in t order)
        while (tptr < CROPDIM && trB == fr) {
            const float4 v0 = lerp4(hp0, h0, twP, twC);
            const float4 v1 = lerp4(hp1, h1, twP, twC);
            if ((tptr & 1) == 0) {
                pend0 = v0;  pend1 = v1;
            } else {
                const float4 m = max4(max4(pend0, v0), max4(pend1, v1));
                ob[(tptr >> 1) * (NPOOL * C4)] = m;
            }
            tptr++;
            if (tptr < CROPDIM) tinfo(tptr, sy, yb, fh, trA, trB, twP, twC);
        }

        hp0 = h0;  hp1 = h1;
        fr++;
        if (tptr < CROPDIM && trA > fr) fr = trA;   // skip unreferenced rows (large sy)
    }
}

extern "C" void kernel_launch(void* const* d_in, const int* in_sizes, int n_in,
                              void* d_out, int out_size) {
    const float* fmap     = (const float*)d_in[0];
    const float* rois     = (const float*)d_in[1];
    const int*   img_size = (const int*)d_in[2];
    float* out = (float*)d_out;

    const int N = in_sizes[1] / 4;   // number of rois
    dim3 grid(N, NPOOL);
    roi_pool_kernel<<<grid, 128>>>(fmap, rois, img_size, out);
}